// round 15
// baseline (speedup 1.0000x reference)
#include <cuda_runtime.h>
#include <cuda_bf16.h>
#include <cuda_fp16.h>
#include <cstdint>

#define N_NODES 50000
#define N_EDGES 1600000
#define IN_C    1433
#define HID_C   128
#define OUT_C   47

#define KP1 1440   // 45 chunks * 32
#define KP2 128
#define KP3 128

// ---------------- scratch (static device globals; no runtime alloc) ----------
__device__ int   g_cnt[N_NODES];
__device__ int   g_rowptr[N_NODES + 1];
__device__ int   g_cursor[N_NODES];
__device__ int   g_srce[N_EDGES];
__device__ float g_dinv[N_NODES];
__device__ int   g_blksum[256];
__device__ int   g_blkoff[256];
__device__ __align__(16) __half g_bufH [(size_t)N_NODES * HID_C]; // gemm1/2 out (gather src), stride 128
__device__ __align__(16) __half g_bufHB[(size_t)N_NODES * HID_C]; // agg out h (gemm2/3 A), stride 128
__device__ __align__(16) __half g_buf48[(size_t)N_NODES * 48];    // gemm3 out, stride 48
// pre-converted weights, padded [KP][136] fp16
__device__ __align__(16) __half g_W1h[KP1 * 136];
__device__ __align__(16) __half g_W2h[KP2 * 136];
__device__ __align__(16) __half g_W3h[KP3 * 136];

// ---------------- graph preprocessing -----------------------------------
__global__ void k_zero_cnt() {
    int i = blockIdx.x * blockDim.x + threadIdx.x;
    if (i < N_NODES) g_cnt[i] = 0;
}
__global__ void k_hist(const int* __restrict__ ei) {
    int e = blockIdx.x * blockDim.x + threadIdx.x;
    if (e < N_EDGES) atomicAdd(&g_cnt[ei[N_EDGES + e]], 1);
}
__global__ void k_scan1() {
    __shared__ int sw[8];
    int i = blockIdx.x * 256 + threadIdx.x;
    int v = (i < N_NODES) ? g_cnt[i] : 0;
    int lane = threadIdx.x & 31, wid = threadIdx.x >> 5;
    #pragma unroll
    for (int o = 16; o > 0; o >>= 1) v += __shfl_down_sync(0xffffffffu, v, o);
    if (lane == 0) sw[wid] = v;
    __syncthreads();
    if (wid == 0) {
        int s = (lane < 8) ? sw[lane] : 0;
        #pragma unroll
        for (int o = 4; o > 0; o >>= 1) s += __shfl_down_sync(0xffu, s, o);
        if (lane == 0) g_blksum[blockIdx.x] = s;
    }
}
__global__ void k_scan2(int nblk) {
    __shared__ int sw[8];
    int t = threadIdx.x, lane = t & 31, wid = t >> 5;
    int v = (t < nblk) ? g_blksum[t] : 0;
    int x = v;
    #pragma unroll
    for (int o = 1; o < 32; o <<= 1) { int y = __shfl_up_sync(0xffffffffu, x, o); if (lane >= o) x += y; }
    if (lane == 31) sw[wid] = x;
    __syncthreads();
    if (wid == 0 && lane < 8) {
        int wx = sw[lane];
        #pragma unroll
        for (int o = 1; o < 8; o <<= 1) { int y = __shfl_up_sync(0xffu, wx, o); if (lane >= o) wx += y; }
        sw[lane] = wx;
    }
    __syncthreads();
    int excl = x - v + (wid ? sw[wid - 1] : 0);
    if (t < nblk) g_blkoff[t] = excl;
}
__global__ void k_scan3() {   // also computes dinv
    __shared__ int sw[8];
    int i = blockIdx.x * 256 + threadIdx.x;
    int t = threadIdx.x, lane = t & 31, wid = t >> 5;
    int v = (i < N_NODES) ? g_cnt[i] : 0;
    int x = v;
    #pragma unroll
    for (int o = 1; o < 32; o <<= 1) { int y = __shfl_up_sync(0xffffffffu, x, o); if (lane >= o) x += y; }
    if (lane == 31) sw[wid] = x;
    __syncthreads();
    if (wid == 0 && lane < 8) {
        int wx = sw[lane];
        #pragma unroll
        for (int o = 1; o < 8; o <<= 1) { int y = __shfl_up_sync(0xffu, wx, o); if (lane >= o) wx += y; }
        sw[lane] = wx;
    }
    __syncthreads();
    int excl = x - v + (wid ? sw[wid - 1] : 0) + g_blkoff[blockIdx.x];
    if (i < N_NODES) {
        g_rowptr[i] = excl; g_cursor[i] = excl;
        g_dinv[i] = rsqrtf((float)v + 1.0f);
    }
    if (i == 0) g_rowptr[N_NODES] = N_EDGES;
}
__global__ void k_fill(const int* __restrict__ ei) {
    int e = blockIdx.x * blockDim.x + threadIdx.x;
    if (e < N_EDGES) {
        int s = ei[e];
        int d = ei[N_EDGES + e];
        int p = atomicAdd(&g_cursor[d], 1);
        g_srce[p] = s;
    }
}

// ---------------- weight prepass: fp32 W[K,Nact] -> fp16 [KP][136] -----------
__global__ void k_prepW(const float* __restrict__ W,
                        __half* __restrict__ oh, int K, int Nact, int KP) {
    int i = blockIdx.x * 256 + threadIdx.x;
    if (i >= KP * 136) return;
    int k = i / 136, n = i - k * 136;
    float v = (k < K && n < Nact) ? W[(size_t)k * Nact + n] : 0.f;
    oh[i] = __float2half_rn(v);
}

// ---------------- shared GEMM plumbing ---------------------------------------
#define A_ST 40
#define B_ST 136
#define OFF_BH 5120            // A: 64*40*2 = 5120 B
#define STAGE_B 13824          // + B: 32*136*2 = 8704 B
#define GEMM_SMEM (2 * STAGE_B)

__device__ __forceinline__ uint32_t smem_u32(const void* p) {
    uint32_t a;
    asm("{ .reg .u64 t; cvta.to.shared.u64 t, %1; cvt.u32.u64 %0, t; }" : "=r"(a) : "l"(p));
    return a;
}
__device__ __forceinline__ void cpa16(uint32_t dst, const void* src) {
    asm volatile("cp.async.cg.shared.global [%0], [%1], 16;" :: "r"(dst), "l"(src));
}
__device__ __forceinline__ void cpa16z(uint32_t dst, const void* src, bool ok) {
    int sz = ok ? 16 : 0;
    asm volatile("cp.async.cg.shared.global [%0], [%1], 16, %2;" :: "r"(dst), "l"(src), "r"(sz));
}
#define CP_COMMIT() asm volatile("cp.async.commit_group;" ::: "memory")
#define CP_WAIT0()  asm volatile("cp.async.wait_group 0;" ::: "memory")

__device__ __forceinline__ void ldmx4(uint32_t* r, uint32_t addr) {
    asm volatile("ldmatrix.sync.aligned.m8n8.x4.shared.b16 {%0,%1,%2,%3}, [%4];"
        : "=r"(r[0]), "=r"(r[1]), "=r"(r[2]), "=r"(r[3]) : "r"(addr));
}
__device__ __forceinline__ void ldmx4t(uint32_t* r, uint32_t addr) {
    asm volatile("ldmatrix.sync.aligned.m8n8.x4.trans.shared.b16 {%0,%1,%2,%3}, [%4];"
        : "=r"(r[0]), "=r"(r[1]), "=r"(r[2]), "=r"(r[3]) : "r"(addr));
}
__device__ __forceinline__ void mma16816h(float* d, const uint32_t* a, const uint32_t* b) {
    asm volatile(
        "mma.sync.aligned.m16n8k16.row.col.f32.f16.f16.f32 "
        "{%0,%1,%2,%3}, {%4,%5,%6,%7}, {%8,%9}, {%0,%1,%2,%3};"
        : "+f"(d[0]), "+f"(d[1]), "+f"(d[2]), "+f"(d[3])
        : "r"(a[0]), "r"(a[1]), "r"(a[2]), "r"(a[3]), "r"(b[0]), "r"(b[1]));
}

// ---------------- GEMM1: fp32 A (LDG+convert), fp16 C stride 128 -------------
__global__ __launch_bounds__(256, 3) void k_gemm1(
    const float* __restrict__ A, const __half* __restrict__ Wh,
    __half* __restrict__ C, int M, int K)
{
    extern __shared__ char smp[];
    const uint32_t sbase = smem_u32(smp);

    const int tid = threadIdx.x, lane = tid & 31, warp = tid >> 5;
    const int wm = warp >> 2, wn = warp & 3;
    const int rowBase = blockIdx.x * 64;

    const int grp = lane >> 3;
    const uint32_t aLane  = (uint32_t)((((grp & 1) * 8 + (lane & 7)) * A_ST + (grp >> 1) * 8) * 2);
    const uint32_t bLaneT = (uint32_t)(((lane & 15) * B_ST) * 2) + (uint32_t)(wn * 64)
                          + (uint32_t)(((lane >> 4) & 1) * 16);

    float acc[2][4][4];
    #pragma unroll
    for (int i = 0; i < 2; i++)
        #pragma unroll
        for (int j = 0; j < 4; j++)
            #pragma unroll
            for (int r = 0; r < 4; r++) acc[i][j][r] = 0.f;

    const int NC = (K + 31) / 32;
    float aReg[8];

    const int aRow = tid >> 4;          // 0..15
    const int aK   = (tid & 15) * 2;    // 0..30, pairs

    auto copyB = [&](int c, uint32_t st) {
        const char* sH = (const char*)(Wh + (size_t)c * 32 * 136);
        uint32_t dH = st + OFF_BH;
        #pragma unroll
        for (int u = 0; u < 3; u++) {
            int i = u * 256 + tid;
            if (i < 544) cpa16(dH + (uint32_t)i * 16, sH + i * 16);
        }
    };
    auto loadA = [&](int c) {
        const int k0 = c * 32;
        #pragma unroll
        for (int u = 0; u < 4; u++) {
            int m = u * 16 + aRow;
            int gm = rowBase + m, gk = k0 + aK;
            bool okm = (gm < M);
            const float* ap = A + (size_t)(okm ? gm : 0) * K;
            aReg[u * 2]     = (okm && gk     < K) ? __ldg(&ap[gk])     : 0.f;
            aReg[u * 2 + 1] = (okm && gk + 1 < K) ? __ldg(&ap[gk + 1]) : 0.f;
        }
    };
    auto convA = [&](uint32_t st) {
        __half* ah = (__half*)(smp + (st - sbase));
        #pragma unroll
        for (int u = 0; u < 4; u++) {
            int m = u * 16 + aRow;
            __half2 h = __floats2half2_rn(aReg[u * 2], aReg[u * 2 + 1]);
            *(__half2*)&ah[m * A_ST + aK] = h;
        }
    };

    copyB(0, sbase);
    CP_COMMIT();
    loadA(0);
    convA(sbase);
    CP_WAIT0();

    for (int c = 0; c < NC; c++) {
        __syncthreads();
        const uint32_t stN = sbase + (uint32_t)((c + 1) & 1) * STAGE_B;
        const bool more = (c + 1 < NC);
        if (more) copyB(c + 1, stN);
        CP_COMMIT();
        if (more) loadA(c + 1);

        const uint32_t st = sbase + (uint32_t)(c & 1) * STAGE_B;
        const uint32_t uAh = st, uBh = st + OFF_BH;
        #pragma unroll
        for (int ks = 0; ks < 2; ks++) {
            uint32_t bh[4][2];
            #pragma unroll
            for (int p = 0; p < 2; p++) {
                uint32_t r4[4];
                ldmx4t(r4, uBh + (uint32_t)(ks * 16 * B_ST * 2) + bLaneT + (uint32_t)(p * 32));
                bh[2 * p][0] = r4[0]; bh[2 * p][1] = r4[1];
                bh[2 * p + 1][0] = r4[2]; bh[2 * p + 1][1] = r4[3];
            }
            #pragma unroll
            for (int mt = 0; mt < 2; mt++) {
                uint32_t ao = aLane + (uint32_t)(((wm * 32 + mt * 16) * A_ST + ks * 16) * 2);
                uint32_t ah[4];
                ldmx4(ah, uAh + ao);
                #pragma unroll
                for (int nt = 0; nt < 4; nt++) mma16816h(acc[mt][nt], ah, bh[nt]);
            }
        }

        if (more) convA(stN);
        CP_WAIT0();
    }

    const int r = lane >> 2, cc = (lane & 3) * 2;
    #pragma unroll
    for (int mt = 0; mt < 2; mt++) {
        int m0 = rowBase + wm * 32 + mt * 16 + r;
        #pragma unroll
        for (int nt = 0; nt < 4; nt++) {
            int n0 = wn * 32 + nt * 8 + cc;
            if (m0 < M)
                *(__half2*)(C + (size_t)m0 * 128 + n0) = __floats2half2_rn(acc[mt][nt][0], acc[mt][nt][1]);
            if (m0 + 8 < M)
                *(__half2*)(C + (size_t)(m0 + 8) * 128 + n0) = __floats2half2_rn(acc[mt][nt][2], acc[mt][nt][3]);
        }
    }
}

// ---------------- GEMM2/3: fp16 A (pure cp.async), fp16 C --------------------
template<bool C48>
__global__ __launch_bounds__(256, 3) void k_gemm_h(
    const __half* __restrict__ A,   // [M,128] fp16
    const __half* __restrict__ Wh,
    __half* __restrict__ C, int M)
{
    extern __shared__ char smp[];
    const uint32_t sbase = smem_u32(smp);

    const int tid = threadIdx.x, lane = tid & 31, warp = tid >> 5;
    const int wm = warp >> 2, wn = warp & 3;
    const int rowBase = blockIdx.x * 64;

    const int grp = lane >> 3;
    const uint32_t aLane  = (uint32_t)((((grp & 1) * 8 + (lane & 7)) * A_ST + (grp >> 1) * 8) * 2);
    const uint32_t bLaneT = (uint32_t)(((lane & 15) * B_ST) * 2) + (uint32_t)(wn * 64)
                          + (uint32_t)(((lane >> 4) & 1) * 16);

    float acc[2][4][4];
    #pragma unroll
    for (int i = 0; i < 2; i++)
        #pragma unroll
        for (int j = 0; j < 4; j++)
            #pragma unroll
            for (int r = 0; r < 4; r++) acc[i][j][r] = 0.f;

    const int NC = 4;  // K = 128

    auto copyAB = [&](int c, uint32_t st) {
        int m = tid >> 2, j = tid & 3;
        int gm = rowBase + m;
        const char* srcA = (const char*)(A + (size_t)(gm < M ? gm : 0) * 128 + c * 32 + j * 8);
        cpa16z(st + (uint32_t)(m * (A_ST * 2) + j * 16), srcA, gm < M);
        const char* sH = (const char*)(Wh + (size_t)c * 32 * 136);
        uint32_t dH = st + OFF_BH;
        #pragma unroll
        for (int u = 0; u < 3; u++) {
            int i = u * 256 + tid;
            if (i < 544) cpa16(dH + (uint32_t)i * 16, sH + i * 16);
        }
    };

    copyAB(0, sbase);
    CP_COMMIT();
    CP_WAIT0();

    for (int c = 0; c < NC; c++) {
        __syncthreads();
        const uint32_t stN = sbase + (uint32_t)((c + 1) & 1) * STAGE_B;
        const bool more = (c + 1 < NC);
        if (more) copyAB(c + 1, stN);
        CP_COMMIT();

        const uint32_t st = sbase + (uint32_t)(c & 1) * STAGE_B;
        const uint32_t uAh = st, uBh = st + OFF_BH;
        #pragma unroll
        for (int ks = 0; ks < 2; ks++) {
            uint32_t bh[4][2];
            #pragma unroll
            for (int p = 0; p < 2; p++) {
                uint32_t r4[4];
                ldmx4t(r4, uBh + (uint32_t)(ks * 16 * B_ST * 2) + bLaneT + (uint32_t)(p * 32));
                bh[2 * p][0] = r4[0]; bh[2 * p][1] = r4[1];
                bh[2 * p + 1][0] = r4[2]; bh[2 * p + 1][1] = r4[3];
            }
            #pragma unroll
            for (int mt = 0; mt < 2; mt++) {
                uint32_t ao = aLane + (uint32_t)(((wm * 32 + mt * 16) * A_ST + ks * 16) * 2);
                uint32_t ah[4];
                ldmx4(ah, uAh + ao);
                #pragma unroll
                for (int nt = 0; nt < 4; nt++) mma16816h(acc[mt][nt], ah, bh[nt]);
            }
        }
        CP_WAIT0();
    }

    const int r = lane >> 2, cc = (lane & 3) * 2;
    #pragma unroll
    for (int mt = 0; mt < 2; mt++) {
        int m0 = rowBase + wm * 32 + mt * 16 + r;
        #pragma unroll
        for (int nt = 0; nt < 4; nt++) {
            int n0 = wn * 32 + nt * 8 + cc;
            if (C48) {
                if (n0 < 48) {
                    if (m0 < M)
                        *(__half2*)(C + (size_t)m0 * 48 + n0) = __floats2half2_rn(acc[mt][nt][0], acc[mt][nt][1]);
                    if (m0 + 8 < M)
                        *(__half2*)(C + (size_t)(m0 + 8) * 48 + n0) = __floats2half2_rn(acc[mt][nt][2], acc[mt][nt][3]);
                }
            } else {
                if (m0 < M)
                    *(__half2*)(C + (size_t)m0 * 128 + n0) = __floats2half2_rn(acc[mt][nt][0], acc[mt][nt][1]);
                if (m0 + 8 < M)
                    *(__half2*)(C + (size_t)(m0 + 8) * 128 + n0) = __floats2half2_rn(acc[mt][nt][2], acc[mt][nt][3]);
            }
        }
    }
}

// ---------------- aggregation: 2 edges/iter, uint4 gathers, shfl bcast -------
// half-warp 0 -> even edges, half-warp 1 -> odd edges; 8 channels/lane.
template<bool RELU>
__global__ __launch_bounds__(128) void k_agg128h(
    const __half* __restrict__ hw, __half* __restrict__ out,
    const float* __restrict__ bias)
{
    int lane = threadIdx.x & 31;
    int node = blockIdx.x * 4 + (threadIdx.x >> 5);
    if (node >= N_NODES) return;

    int beg = g_rowptr[node];
    int end = g_rowptr[node + 1];
    float dd = g_dinv[node];
    const int half = lane >> 4, sub = lane & 15;

    float acc[8];
    #pragma unroll
    for (int i = 0; i < 8; i++) acc[i] = 0.f;

    for (int base = beg; base < end; base += 32) {
        int n = end - base; if (n > 32) n = 32;
        int si = 0; float swt = 0.f;
        if (lane < n) { si = g_srce[base + lane]; swt = g_dinv[si] * dd; }
        #pragma unroll 4
        for (int it = 0; it < 16; it++) {
            int j = 2 * it + half;
            if (2 * it >= n) break;                 // warp-uniform
            int   ss = __shfl_sync(0xffffffffu, si,  j);
            float ww = __shfl_sync(0xffffffffu, swt, j);
            uint4 raw = *(const uint4*)(hw + (size_t)ss * 128 + sub * 8);
            float2 f0 = __half22float2(*(__half2*)&raw.x);
            float2 f1 = __half22float2(*(__half2*)&raw.y);
            float2 f2 = __half22float2(*(__half2*)&raw.z);
            float2 f3 = __half22float2(*(__half2*)&raw.w);
            acc[0] += f0.x * ww; acc[1] += f0.y * ww;
            acc[2] += f1.x * ww; acc[3] += f1.y * ww;
            acc[4] += f2.x * ww; acc[5] += f2.y * ww;
            acc[6] += f3.x * ww; acc[7] += f3.y * ww;
        }
    }

    // merge even/odd halves
    #pragma unroll
    for (int i = 0; i < 8; i++) acc[i] += __shfl_xor_sync(0xffffffffu, acc[i], 16);

    if (half == 0) {
        {   // self-loop
            float ww = dd * dd;
            uint4 raw = *(const uint4*)(hw + (size_t)node * 128 + sub * 8);
            float2 f0 = __half22float2(*(__half2*)&raw.x);
            float2 f1 = __half22float2(*(__half2*)&raw.y);
            float2 f2 = __half22float2(*(__half2*)&raw.z);
            float2 f3 = __half22float2(*(__half2*)&raw.w);
            acc[0] += f0.x * ww; acc[1] += f0.y * ww;
            acc[2] += f1.x * ww; acc[3] += f1.y * ww;
            acc[4] += f2.x * ww; acc[5] += f2.y * ww;
            acc[6] += f3.x * ww; acc[7] += f3.y * ww;
        }
        float4 b0 = *(const float4*)(bias + sub * 8);
        float4 b1 = *(const float4*)(bias + sub * 8 + 4);
        acc[0] += b0.x; acc[1] += b0.y; acc[2] += b0.z; acc[3] += b0.w;
        acc[4] += b1.x; acc[5] += b1.y; acc[6] += b1.z; acc[7] += b1.w;
        if (RELU) {
            #pragma unroll
            for (int i = 0; i < 8; i++) acc[i] = fmaxf(acc[i], 0.f);
        }
        __half2 o0 = __floats2half2_rn(acc[0], acc[1]);
        __half2 o1 = __floats2half2_rn(acc[2], acc[3]);
        __half2 o2 = __floats2half2_rn(acc[4], acc[5]);
        __half2 o3 = __floats2half2_rn(acc[6], acc[7]);
        uint4 pk = { *(uint32_t*)&o0, *(uint32_t*)&o1, *(uint32_t*)&o2, *(uint32_t*)&o3 };
        *(uint4*)(out + (size_t)node * 128 + sub * 8) = pk;
    }
}

// final layer: gather fp16 stride-48 rows, fp32 out
__global__ __launch_bounds__(128) void k_agg47h(const float* __restrict__ bias,
                                                float* __restrict__ out) {
    const __half* hw = g_buf48;   // stride 48 halfs
    __shared__ int   s_idx[4][32];
    __shared__ float s_wt [4][32];

    int w    = threadIdx.x >> 5;
    int lane = threadIdx.x & 31;
    int node = blockIdx.x * 4 + w;
    if (node >= N_NODES) return;

    int beg = g_rowptr[node];
    int end = g_rowptr[node + 1];
    float dd = g_dinv[node];
    bool act = (lane < 24);       // lanes 0-23 cover 48 cols as half2

    float a0 = 0.f, a1 = 0.f;

    for (int base = beg; base < end; base += 32) {
        int n = end - base; if (n > 32) n = 32;
        int si = 0; float swt = 0.f;
        if (lane < n) { si = g_srce[base + lane]; swt = g_dinv[si] * dd; }
        s_idx[w][lane] = si; s_wt[w][lane] = swt;
        __syncwarp();
        for (int j = 0; j < n; j++) {
            int ss = s_idx[w][j]; float ww = s_wt[w][j];
            if (act) {
                uint32_t raw = *(const uint32_t*)(hw + (size_t)ss * 48 + lane * 2);
                float2 f = __half22float2(*(__half2*)&raw);
                a0 += f.x * ww; a1 += f.y * ww;
            }
        }
        __syncwarp();
    }
    {   // self-loop
        float ww = dd * dd;
        if (act) {
            uint32_t raw = *(const uint32_t*)(hw + (size_t)node * 48 + lane * 2);
            float2 f = __half22float2(*(__half2*)&raw);
            a0 += f.x * ww; a1 += f.y * ww;
        }
    }
    if (act) {
        int c0 = lane * 2;
        out[(size_t)node * OUT_C + c0] = a0 + bias[c0];
        if (c0 + 1 < OUT_C)
            out[(size_t)node * OUT_C + c0 + 1] = a1 + bias[c0 + 1];
    }
}

// ---------------- launch ------------------------------------------------
extern "C" void kernel_launch(void* const* d_in, const int* in_sizes, int n_in,
                              void* d_out, int out_size) {
    const float* x  = (const float*)d_in[0];
    const int*   ei = (const int*)  d_in[1];
    const float* W1 = (const float*)d_in[2];
    const float* b1 = (const float*)d_in[3];
    const float* W2 = (const float*)d_in[4];
    const float* b2 = (const float*)d_in[5];
    const float* W3 = (const float*)d_in[6];
    const float* b3 = (const float*)d_in[7];
    float* out = (float*)d_out;

    void *pH, *pHB, *p48, *p1h, *p2h, *p3h;
    cudaGetSymbolAddress(&pH,  g_bufH);
    cudaGetSymbolAddress(&pHB, g_bufHB);
    cudaGetSymbolAddress(&p48, g_buf48);
    cudaGetSymbolAddress(&p1h, g_W1h);
    cudaGetSymbolAddress(&p2h, g_W2h);
    cudaGetSymbolAddress(&p3h, g_W3h);

    cudaFuncSetAttribute((const void*)&k_gemm1,         cudaFuncAttributeMaxDynamicSharedMemorySize, GEMM_SMEM);
    cudaFuncSetAttribute((const void*)&k_gemm_h<false>, cudaFuncAttributeMaxDynamicSharedMemorySize, GEMM_SMEM);
    cudaFuncSetAttribute((const void*)&k_gemm_h<true>,  cudaFuncAttributeMaxDynamicSharedMemorySize, GEMM_SMEM);

    static cudaStream_t s2 = nullptr;
    static cudaEvent_t evFork = nullptr, evCSR = nullptr;
    if (!s2) {
        cudaStreamCreateWithFlags(&s2, cudaStreamNonBlocking);
        cudaEventCreateWithFlags(&evFork, cudaEventDisableTiming);
        cudaEventCreateWithFlags(&evCSR,  cudaEventDisableTiming);
    }

    const int NB = (N_NODES + 255) / 256;
    const int EB = (N_EDGES + 255) / 256;
    const int gemmGrid = (N_NODES + 63) / 64;    // 782
    const int aggGrid  = (N_NODES + 3) / 4;

    // fork side stream at t=0: full CSR build + weight prep 2/3
    cudaEventRecord(evFork, 0);
    cudaStreamWaitEvent(s2, evFork, 0);
    k_zero_cnt<<<NB, 256, 0, s2>>>();
    k_hist<<<EB, 256, 0, s2>>>(ei);
    // main: GEMM1 path immediately
    k_prepW<<<(KP1 * 136 + 255) / 256, 256>>>(W1, (__half*)p1h, IN_C, HID_C, KP1);
    k_gemm1<<<gemmGrid, 256, GEMM_SMEM>>>(x, (const __half*)p1h,
                                          (__half*)pH, N_NODES, IN_C);
    // side stream: rest of CSR + weight prep
    k_scan1<<<NB, 256, 0, s2>>>();
    k_scan2<<<1, 256, 0, s2>>>(NB);
    k_scan3<<<NB, 256, 0, s2>>>();
    k_fill<<<EB, 256, 0, s2>>>(ei);
    k_prepW<<<(KP2 * 136 + 255) / 256, 256, 0, s2>>>(W2, (__half*)p2h, HID_C, HID_C, KP2);
    k_prepW<<<(KP3 * 136 + 255) / 256, 256, 0, s2>>>(W3, (__half*)p3h, HID_C, OUT_C, KP3);
    cudaEventRecord(evCSR, s2);

    // join, then the serial layer chain (best-known structure)
    cudaStreamWaitEvent(0, evCSR, 0);
    k_agg128h<true><<<aggGrid, 128>>>((const __half*)pH, (__half*)pHB, b1);
    k_gemm_h<false><<<gemmGrid, 256, GEMM_SMEM>>>((const __half*)pHB, (const __half*)p2h,
                                                  (__half*)pH, N_NODES);
    k_agg128h<true><<<aggGrid, 128>>>((const __half*)pH, (__half*)pHB, b2);
    k_gemm_h<true><<<gemmGrid, 256, GEMM_SMEM>>>((const __half*)pHB, (const __half*)p3h,
                                                 (__half*)p48, N_NODES);
    k_agg47h<<<aggGrid, 128>>>(b3, out);
}

// round 16
// speedup vs baseline: 1.1061x; 1.1061x over previous
#include <cuda_runtime.h>
#include <cuda_bf16.h>
#include <cuda_fp16.h>
#include <cstdint>

#define N_NODES 50000
#define N_EDGES 1600000
#define IN_C    1433
#define HID_C   128
#define OUT_C   47

#define KP1 1472   // 23 chunks * 64
#define KP2 128
#define KP3 128

// ---------------- scratch (static device globals; no runtime alloc) ----------
__device__ int   g_cnt[N_NODES];
__device__ int   g_rowptr[N_NODES + 1];
__device__ int   g_cursor[N_NODES];
__device__ int   g_srce[N_EDGES];
__device__ float g_dinv[N_NODES];
__device__ int   g_blksum[256];
__device__ int   g_blkoff[256];
__device__ __align__(16) __half g_bufH [(size_t)N_NODES * HID_C]; // gemm1/2 out (gather src), stride 128
__device__ __align__(16) __half g_bufHB[(size_t)N_NODES * HID_C]; // agg out h (gemm2/3 A), stride 128
__device__ __align__(16) __half g_buf48[(size_t)N_NODES * 48];    // gemm3 out, stride 48
// pre-converted weights, padded [KP][136] fp16
__device__ __align__(16) __half g_W1h[KP1 * 136];
__device__ __align__(16) __half g_W2h[KP2 * 136];
__device__ __align__(16) __half g_W3h[KP3 * 136];

// ---------------- graph preprocessing -----------------------------------
__global__ void k_zero_cnt() {
    int i = blockIdx.x * blockDim.x + threadIdx.x;
    if (i < N_NODES) g_cnt[i] = 0;
}
__global__ void k_hist(const int* __restrict__ ei) {
    int e = blockIdx.x * blockDim.x + threadIdx.x;
    if (e < N_EDGES) atomicAdd(&g_cnt[ei[N_EDGES + e]], 1);
}
__global__ void k_scan1() {
    __shared__ int sw[8];
    int i = blockIdx.x * 256 + threadIdx.x;
    int v = (i < N_NODES) ? g_cnt[i] : 0;
    int lane = threadIdx.x & 31, wid = threadIdx.x >> 5;
    #pragma unroll
    for (int o = 16; o > 0; o >>= 1) v += __shfl_down_sync(0xffffffffu, v, o);
    if (lane == 0) sw[wid] = v;
    __syncthreads();
    if (wid == 0) {
        int s = (lane < 8) ? sw[lane] : 0;
        #pragma unroll
        for (int o = 4; o > 0; o >>= 1) s += __shfl_down_sync(0xffu, s, o);
        if (lane == 0) g_blksum[blockIdx.x] = s;
    }
}
__global__ void k_scan2(int nblk) {
    __shared__ int sw[8];
    int t = threadIdx.x, lane = t & 31, wid = t >> 5;
    int v = (t < nblk) ? g_blksum[t] : 0;
    int x = v;
    #pragma unroll
    for (int o = 1; o < 32; o <<= 1) { int y = __shfl_up_sync(0xffffffffu, x, o); if (lane >= o) x += y; }
    if (lane == 31) sw[wid] = x;
    __syncthreads();
    if (wid == 0 && lane < 8) {
        int wx = sw[lane];
        #pragma unroll
        for (int o = 1; o < 8; o <<= 1) { int y = __shfl_up_sync(0xffu, wx, o); if (lane >= o) wx += y; }
        sw[lane] = wx;
    }
    __syncthreads();
    int excl = x - v + (wid ? sw[wid - 1] : 0);
    if (t < nblk) g_blkoff[t] = excl;
}
__global__ void k_scan3() {   // also computes dinv
    __shared__ int sw[8];
    int i = blockIdx.x * 256 + threadIdx.x;
    int t = threadIdx.x, lane = t & 31, wid = t >> 5;
    int v = (i < N_NODES) ? g_cnt[i] : 0;
    int x = v;
    #pragma unroll
    for (int o = 1; o < 32; o <<= 1) { int y = __shfl_up_sync(0xffffffffu, x, o); if (lane >= o) x += y; }
    if (lane == 31) sw[wid] = x;
    __syncthreads();
    if (wid == 0 && lane < 8) {
        int wx = sw[lane];
        #pragma unroll
        for (int o = 1; o < 8; o <<= 1) { int y = __shfl_up_sync(0xffu, wx, o); if (lane >= o) wx += y; }
        sw[lane] = wx;
    }
    __syncthreads();
    int excl = x - v + (wid ? sw[wid - 1] : 0) + g_blkoff[blockIdx.x];
    if (i < N_NODES) {
        g_rowptr[i] = excl; g_cursor[i] = excl;
        g_dinv[i] = rsqrtf((float)v + 1.0f);
    }
    if (i == 0) g_rowptr[N_NODES] = N_EDGES;
}
__global__ void k_fill(const int* __restrict__ ei) {
    int e = blockIdx.x * blockDim.x + threadIdx.x;
    if (e < N_EDGES) {
        int s = ei[e];
        int d = ei[N_EDGES + e];
        int p = atomicAdd(&g_cursor[d], 1);
        g_srce[p] = s;
    }
}

// ---------------- weight prepass: fp32 W[K,Nact] -> fp16 [KP][136] -----------
__global__ void k_prepW(const float* __restrict__ W,
                        __half* __restrict__ oh, int K, int Nact, int KP) {
    int i = blockIdx.x * 256 + threadIdx.x;
    if (i >= KP * 136) return;
    int k = i / 136, n = i - k * 136;
    float v = (k < K && n < Nact) ? W[(size_t)k * Nact + n] : 0.f;
    oh[i] = __float2half_rn(v);
}

// ---------------- shared GEMM plumbing ---------------------------------------
#define A_ST 40
#define B_ST 136
#define OFF_BH 5120            // gemm2/3: A 64*40*2 = 5120 B
#define STAGE_B 13824          // + B: 32*136*2 = 8704 B
#define GEMM_SMEM (2 * STAGE_B)
// gemm1 (K-chunk 64):
#define A_ST1 72
#define OFF_BH1 9216           // A: 64*72*2
#define STAGE_B1 26624         // + B: 64*136*2 = 17408 B
#define GEMM1_SMEM (2 * STAGE_B1)

__device__ __forceinline__ uint32_t smem_u32(const void* p) {
    uint32_t a;
    asm("{ .reg .u64 t; cvta.to.shared.u64 t, %1; cvt.u32.u64 %0, t; }" : "=r"(a) : "l"(p));
    return a;
}
__device__ __forceinline__ void cpa16(uint32_t dst, const void* src) {
    asm volatile("cp.async.cg.shared.global [%0], [%1], 16;" :: "r"(dst), "l"(src));
}
__device__ __forceinline__ void cpa16z(uint32_t dst, const void* src, bool ok) {
    int sz = ok ? 16 : 0;
    asm volatile("cp.async.cg.shared.global [%0], [%1], 16, %2;" :: "r"(dst), "l"(src), "r"(sz));
}
#define CP_COMMIT() asm volatile("cp.async.commit_group;" ::: "memory")
#define CP_WAIT0()  asm volatile("cp.async.wait_group 0;" ::: "memory")

__device__ __forceinline__ void ldmx4(uint32_t* r, uint32_t addr) {
    asm volatile("ldmatrix.sync.aligned.m8n8.x4.shared.b16 {%0,%1,%2,%3}, [%4];"
        : "=r"(r[0]), "=r"(r[1]), "=r"(r[2]), "=r"(r[3]) : "r"(addr));
}
__device__ __forceinline__ void ldmx4t(uint32_t* r, uint32_t addr) {
    asm volatile("ldmatrix.sync.aligned.m8n8.x4.trans.shared.b16 {%0,%1,%2,%3}, [%4];"
        : "=r"(r[0]), "=r"(r[1]), "=r"(r[2]), "=r"(r[3]) : "r"(addr));
}
__device__ __forceinline__ void mma16816h(float* d, const uint32_t* a, const uint32_t* b) {
    asm volatile(
        "mma.sync.aligned.m16n8k16.row.col.f32.f16.f16.f32 "
        "{%0,%1,%2,%3}, {%4,%5,%6,%7}, {%8,%9}, {%0,%1,%2,%3};"
        : "+f"(d[0]), "+f"(d[1]), "+f"(d[2]), "+f"(d[3])
        : "r"(a[0]), "r"(a[1]), "r"(a[2]), "r"(a[3]), "r"(b[0]), "r"(b[1]));
}

// ---------------- GEMM1: fp32 A (LDG+convert), fp16 C, K-chunk 64 ------------
__global__ __launch_bounds__(256, 3) void k_gemm1(
    const float* __restrict__ A, const __half* __restrict__ Wh,
    __half* __restrict__ C, int M, int K)
{
    extern __shared__ char smp[];
    const uint32_t sbase = smem_u32(smp);

    const int tid = threadIdx.x, lane = tid & 31, warp = tid >> 5;
    const int wm = warp >> 2, wn = warp & 3;
    const int rowBase = blockIdx.x * 64;

    const int grp = lane >> 3;
    const uint32_t aLane  = (uint32_t)((((grp & 1) * 8 + (lane & 7)) * A_ST1 + (grp >> 1) * 8) * 2);
    const uint32_t bLaneT = (uint32_t)(((lane & 15) * B_ST) * 2) + (uint32_t)(wn * 64)
                          + (uint32_t)(((lane >> 4) & 1) * 16);

    float acc[2][4][4];
    #pragma unroll
    for (int i = 0; i < 2; i++)
        #pragma unroll
        for (int j = 0; j < 4; j++)
            #pragma unroll
            for (int r = 0; r < 4; r++) acc[i][j][r] = 0.f;

    const int NC = (K + 63) / 64;    // 23
    float aReg[16];

    const int aRow = tid >> 4;          // 0..15
    const int aK   = (tid & 15) * 2;    // 0..30, pairs within a 32-k half

    auto copyB = [&](int c, uint32_t st) {
        const char* sH = (const char*)(Wh + (size_t)c * 64 * 136);
        uint32_t dH = st + OFF_BH1;
        #pragma unroll
        for (int u = 0; u < 5; u++) {
            int i = u * 256 + tid;
            if (i < 1088) cpa16(dH + (uint32_t)i * 16, sH + i * 16);
        }
    };
    auto loadA = [&](int c) {
        const int k0 = c * 64;
        #pragma unroll
        for (int u = 0; u < 4; u++) {
            int m = u * 16 + aRow;
            int gm = rowBase + m;
            bool okm = (gm < M);
            const float* ap = A + (size_t)(okm ? gm : 0) * K;
            #pragma unroll
            for (int h = 0; h < 2; h++) {
                int gk = k0 + h * 32 + aK;
                aReg[(u * 2 + h) * 2]     = (okm && gk     < K) ? __ldg(&ap[gk])     : 0.f;
                aReg[(u * 2 + h) * 2 + 1] = (okm && gk + 1 < K) ? __ldg(&ap[gk + 1]) : 0.f;
            }
        }
    };
    auto convA = [&](uint32_t st) {
        __half* ah = (__half*)(smp + (st - sbase));
        #pragma unroll
        for (int u = 0; u < 4; u++) {
            int m = u * 16 + aRow;
            #pragma unroll
            for (int h = 0; h < 2; h++) {
                __half2 hh = __floats2half2_rn(aReg[(u * 2 + h) * 2], aReg[(u * 2 + h) * 2 + 1]);
                *(__half2*)&ah[m * A_ST1 + h * 32 + aK] = hh;
            }
        }
    };

    copyB(0, sbase);
    CP_COMMIT();
    loadA(0);
    convA(sbase);
    CP_WAIT0();

    for (int c = 0; c < NC; c++) {
        __syncthreads();
        const uint32_t stN = sbase + (uint32_t)((c + 1) & 1) * STAGE_B1;
        const bool more = (c + 1 < NC);
        if (more) copyB(c + 1, stN);
        CP_COMMIT();
        if (more) loadA(c + 1);

        const uint32_t st = sbase + (uint32_t)(c & 1) * STAGE_B1;
        const uint32_t uAh = st, uBh = st + OFF_BH1;
        #pragma unroll
        for (int ks = 0; ks < 4; ks++) {
            uint32_t bh[4][2];
            #pragma unroll
            for (int p = 0; p < 2; p++) {
                uint32_t r4[4];
                ldmx4t(r4, uBh + (uint32_t)(ks * 16 * B_ST * 2) + bLaneT + (uint32_t)(p * 32));
                bh[2 * p][0] = r4[0]; bh[2 * p][1] = r4[1];
                bh[2 * p + 1][0] = r4[2]; bh[2 * p + 1][1] = r4[3];
            }
            #pragma unroll
            for (int mt = 0; mt < 2; mt++) {
                uint32_t ao = aLane + (uint32_t)(((wm * 32 + mt * 16) * A_ST1 + ks * 16) * 2);
                uint32_t ah[4];
                ldmx4(ah, uAh + ao);
                #pragma unroll
                for (int nt = 0; nt < 4; nt++) mma16816h(acc[mt][nt], ah, bh[nt]);
            }
        }

        if (more) convA(stN);
        CP_WAIT0();
    }

    const int r = lane >> 2, cc = (lane & 3) * 2;
    #pragma unroll
    for (int mt = 0; mt < 2; mt++) {
        int m0 = rowBase + wm * 32 + mt * 16 + r;
        #pragma unroll
        for (int nt = 0; nt < 4; nt++) {
            int n0 = wn * 32 + nt * 8 + cc;
            if (m0 < M)
                *(__half2*)(C + (size_t)m0 * 128 + n0) = __floats2half2_rn(acc[mt][nt][0], acc[mt][nt][1]);
            if (m0 + 8 < M)
                *(__half2*)(C + (size_t)(m0 + 8) * 128 + n0) = __floats2half2_rn(acc[mt][nt][2], acc[mt][nt][3]);
        }
    }
}

// ---------------- GEMM2/3: fp16 A (pure cp.async), fp16 C --------------------
template<bool C48>
__global__ __launch_bounds__(256, 3) void k_gemm_h(
    const __half* __restrict__ A,   // [M,128] fp16
    const __half* __restrict__ Wh,
    __half* __restrict__ C, int M)
{
    extern __shared__ char smp[];
    const uint32_t sbase = smem_u32(smp);

    const int tid = threadIdx.x, lane = tid & 31, warp = tid >> 5;
    const int wm = warp >> 2, wn = warp & 3;
    const int rowBase = blockIdx.x * 64;

    const int grp = lane >> 3;
    const uint32_t aLane  = (uint32_t)((((grp & 1) * 8 + (lane & 7)) * A_ST + (grp >> 1) * 8) * 2);
    const uint32_t bLaneT = (uint32_t)(((lane & 15) * B_ST) * 2) + (uint32_t)(wn * 64)
                          + (uint32_t)(((lane >> 4) & 1) * 16);

    float acc[2][4][4];
    #pragma unroll
    for (int i = 0; i < 2; i++)
        #pragma unroll
        for (int j = 0; j < 4; j++)
            #pragma unroll
            for (int r = 0; r < 4; r++) acc[i][j][r] = 0.f;

    const int NC = 4;  // K = 128

    auto copyAB = [&](int c, uint32_t st) {
        int m = tid >> 2, j = tid & 3;
        int gm = rowBase + m;
        const char* srcA = (const char*)(A + (size_t)(gm < M ? gm : 0) * 128 + c * 32 + j * 8);
        cpa16z(st + (uint32_t)(m * (A_ST * 2) + j * 16), srcA, gm < M);
        const char* sH = (const char*)(Wh + (size_t)c * 32 * 136);
        uint32_t dH = st + OFF_BH;
        #pragma unroll
        for (int u = 0; u < 3; u++) {
            int i = u * 256 + tid;
            if (i < 544) cpa16(dH + (uint32_t)i * 16, sH + i * 16);
        }
    };

    copyAB(0, sbase);
    CP_COMMIT();
    CP_WAIT0();

    for (int c = 0; c < NC; c++) {
        __syncthreads();
        const uint32_t stN = sbase + (uint32_t)((c + 1) & 1) * STAGE_B;
        const bool more = (c + 1 < NC);
        if (more) copyAB(c + 1, stN);
        CP_COMMIT();

        const uint32_t st = sbase + (uint32_t)(c & 1) * STAGE_B;
        const uint32_t uAh = st, uBh = st + OFF_BH;
        #pragma unroll
        for (int ks = 0; ks < 2; ks++) {
            uint32_t bh[4][2];
            #pragma unroll
            for (int p = 0; p < 2; p++) {
                uint32_t r4[4];
                ldmx4t(r4, uBh + (uint32_t)(ks * 16 * B_ST * 2) + bLaneT + (uint32_t)(p * 32));
                bh[2 * p][0] = r4[0]; bh[2 * p][1] = r4[1];
                bh[2 * p + 1][0] = r4[2]; bh[2 * p + 1][1] = r4[3];
            }
            #pragma unroll
            for (int mt = 0; mt < 2; mt++) {
                uint32_t ao = aLane + (uint32_t)(((wm * 32 + mt * 16) * A_ST + ks * 16) * 2);
                uint32_t ah[4];
                ldmx4(ah, uAh + ao);
                #pragma unroll
                for (int nt = 0; nt < 4; nt++) mma16816h(acc[mt][nt], ah, bh[nt]);
            }
        }
        CP_WAIT0();
    }

    const int r = lane >> 2, cc = (lane & 3) * 2;
    #pragma unroll
    for (int mt = 0; mt < 2; mt++) {
        int m0 = rowBase + wm * 32 + mt * 16 + r;
        #pragma unroll
        for (int nt = 0; nt < 4; nt++) {
            int n0 = wn * 32 + nt * 8 + cc;
            if (C48) {
                if (n0 < 48) {
                    if (m0 < M)
                        *(__half2*)(C + (size_t)m0 * 48 + n0) = __floats2half2_rn(acc[mt][nt][0], acc[mt][nt][1]);
                    if (m0 + 8 < M)
                        *(__half2*)(C + (size_t)(m0 + 8) * 48 + n0) = __floats2half2_rn(acc[mt][nt][2], acc[mt][nt][3]);
                }
            } else {
                if (m0 < M)
                    *(__half2*)(C + (size_t)m0 * 128 + n0) = __floats2half2_rn(acc[mt][nt][0], acc[mt][nt][1]);
                if (m0 + 8 < M)
                    *(__half2*)(C + (size_t)(m0 + 8) * 128 + n0) = __floats2half2_rn(acc[mt][nt][2], acc[mt][nt][3]);
            }
        }
    }
}

// ---------------- aggregation (fp16 gather, fp32 accum, fp16 h out) ----------
template<bool RELU>
__global__ __launch_bounds__(128) void k_agg128h(
    const __half* __restrict__ hw, __half* __restrict__ out,
    const float* __restrict__ bias)
{
    __shared__ int   s_idx[4][32];
    __shared__ float s_wt [4][32];

    int w    = threadIdx.x >> 5;
    int lane = threadIdx.x & 31;
    int node = blockIdx.x * 4 + w;
    if (node >= N_NODES) return;

    int beg = g_rowptr[node];
    int end = g_rowptr[node + 1];
    float dd = g_dinv[node];

    float ax = 0.f, ay = 0.f, az = 0.f, aw = 0.f;

    for (int base = beg; base < end; base += 32) {
        int n = end - base; if (n > 32) n = 32;
        int si = 0; float swt = 0.f;
        if (lane < n) { si = g_srce[base + lane]; swt = g_dinv[si] * dd; }
        s_idx[w][lane] = si; s_wt[w][lane] = swt;
        __syncwarp();
        if (n == 32) {
            #pragma unroll 8
            for (int j = 0; j < 32; j++) {
                int ss = s_idx[w][j]; float ww = s_wt[w][j];
                uint2 raw = *(const uint2*)(hw + (size_t)ss * 128 + lane * 4);
                float2 f0 = __half22float2(*(__half2*)&raw.x);
                float2 f1 = __half22float2(*(__half2*)&raw.y);
                ax += f0.x * ww; ay += f0.y * ww; az += f1.x * ww; aw += f1.y * ww;
            }
        } else {
            for (int j = 0; j < n; j++) {
                int ss = s_idx[w][j]; float ww = s_wt[w][j];
                uint2 raw = *(const uint2*)(hw + (size_t)ss * 128 + lane * 4);
                float2 f0 = __half22float2(*(__half2*)&raw.x);
                float2 f1 = __half22float2(*(__half2*)&raw.y);
                ax += f0.x * ww; ay += f0.y * ww; az += f1.x * ww; aw += f1.y * ww;
            }
        }
        __syncwarp();
    }

    {   // self-loop
        float ww = dd * dd;
        uint2 raw = *(const uint2*)(hw + (size_t)node * 128 + lane * 4);
        float2 f0 = __half22float2(*(__half2*)&raw.x);
        float2 f1 = __half22float2(*(__half2*)&raw.y);
        ax += f0.x * ww; ay += f0.y * ww; az += f1.x * ww; aw += f1.y * ww;
    }
    float4 b = *(const float4*)(bias + lane * 4);
    ax += b.x; ay += b.y; az += b.z; aw += b.w;
    if (RELU) {
        ax = fmaxf(ax, 0.f); ay = fmaxf(ay, 0.f);
        az = fmaxf(az, 0.f); aw = fmaxf(aw, 0.f);
    }
    __half2 o0 = __floats2half2_rn(ax, ay);
    __half2 o1 = __floats2half2_rn(az, aw);
    uint2 pk = { *(uint32_t*)&o0, *(uint32_t*)&o1 };
    *(uint2*)(out + (size_t)node * 128 + lane * 4) = pk;
}

// final layer: gather fp16 stride-48 rows, fp32 out
__global__ __launch_bounds__(128) void k_agg47h(const float* __restrict__ bias,
                                                float* __restrict__ out) {
    const __half* hw = g_buf48;   // stride 48 halfs
    __shared__ int   s_idx[4][32];
    __shared__ float s_wt [4][32];

    int w    = threadIdx.x >> 5;
    int lane = threadIdx.x & 31;
    int node = blockIdx.x * 4 + w;
    if (node >= N_NODES) return;

    int beg = g_rowptr[node];
    int end = g_rowptr[node + 1];
    float dd = g_dinv[node];
    bool act = (lane < 24);       // lanes 0-23 cover 48 cols as half2

    float a0 = 0.f, a1 = 0.f;

    for (int base = beg; base < end; base += 32) {
        int n = end - base; if (n > 32) n = 32;
        int si = 0; float swt = 0.f;
        if (lane < n) { si = g_srce[base + lane]; swt = g_dinv[si] * dd; }
        s_idx[w][lane] = si; s_wt[w][lane] = swt;
        __syncwarp();
        for (int j = 0; j < n; j++) {
            int ss = s_idx[w][j]; float ww = s_wt[w][j];
            if (act) {
                uint32_t raw = *(const uint32_t*)(hw + (size_t)ss * 48 + lane * 2);
                float2 f = __half22float2(*(__half2*)&raw);
                a0 += f.x * ww; a1 += f.y * ww;
            }
        }
        __syncwarp();
    }
    {   // self-loop
        float ww = dd * dd;
        if (act) {
            uint32_t raw = *(const uint32_t*)(hw + (size_t)node * 48 + lane * 2);
            float2 f = __half22float2(*(__half2*)&raw);
            a0 += f.x * ww; a1 += f.y * ww;
        }
    }
    if (act) {
        int c0 = lane * 2;
        out[(size_t)node * OUT_C + c0] = a0 + bias[c0];
        if (c0 + 1 < OUT_C)
            out[(size_t)node * OUT_C + c0 + 1] = a1 + bias[c0 + 1];
    }
}

// ---------------- launch ------------------------------------------------
extern "C" void kernel_launch(void* const* d_in, const int* in_sizes, int n_in,
                              void* d_out, int out_size) {
    const float* x  = (const float*)d_in[0];
    const int*   ei = (const int*)  d_in[1];
    const float* W1 = (const float*)d_in[2];
    const float* b1 = (const float*)d_in[3];
    const float* W2 = (const float*)d_in[4];
    const float* b2 = (const float*)d_in[5];
    const float* W3 = (const float*)d_in[6];
    const float* b3 = (const float*)d_in[7];
    float* out = (float*)d_out;

    void *pH, *pHB, *p48, *p1h, *p2h, *p3h;
    cudaGetSymbolAddress(&pH,  g_bufH);
    cudaGetSymbolAddress(&pHB, g_bufHB);
    cudaGetSymbolAddress(&p48, g_buf48);
    cudaGetSymbolAddress(&p1h, g_W1h);
    cudaGetSymbolAddress(&p2h, g_W2h);
    cudaGetSymbolAddress(&p3h, g_W3h);

    cudaFuncSetAttribute((const void*)&k_gemm1,         cudaFuncAttributeMaxDynamicSharedMemorySize, GEMM1_SMEM);
    cudaFuncSetAttribute((const void*)&k_gemm_h<false>, cudaFuncAttributeMaxDynamicSharedMemorySize, GEMM_SMEM);
    cudaFuncSetAttribute((const void*)&k_gemm_h<true>,  cudaFuncAttributeMaxDynamicSharedMemorySize, GEMM_SMEM);

    static cudaStream_t s2 = nullptr;
    static cudaEvent_t evFork = nullptr, evCSR = nullptr;
    if (!s2) {
        cudaStreamCreateWithFlags(&s2, cudaStreamNonBlocking);
        cudaEventCreateWithFlags(&evFork, cudaEventDisableTiming);
        cudaEventCreateWithFlags(&evCSR,  cudaEventDisableTiming);
    }

    const int NB = (N_NODES + 255) / 256;
    const int EB = (N_EDGES + 255) / 256;
    const int gemmGrid = (N_NODES + 63) / 64;    // 782
    const int aggGrid  = (N_NODES + 3) / 4;

    // fork side stream at t=0: full CSR build + weight prep 2/3
    cudaEventRecord(evFork, 0);
    cudaStreamWaitEvent(s2, evFork, 0);
    k_zero_cnt<<<NB, 256, 0, s2>>>();
    k_hist<<<EB, 256, 0, s2>>>(ei);
    // main: GEMM1 path immediately
    k_prepW<<<(KP1 * 136 + 255) / 256, 256>>>(W1, (__half*)p1h, IN_C, HID_C, KP1);
    k_gemm1<<<gemmGrid, 256, GEMM1_SMEM>>>(x, (const __half*)p1h,
                                           (__half*)pH, N_NODES, IN_C);
    // side stream: rest of CSR + weight prep
    k_scan1<<<NB, 256, 0, s2>>>();
    k_scan2<<<1, 256, 0, s2>>>(NB);
    k_scan3<<<NB, 256, 0, s2>>>();
    k_fill<<<EB, 256, 0, s2>>>(ei);
    k_prepW<<<(KP2 * 136 + 255) / 256, 256, 0, s2>>>(W2, (__half*)p2h, HID_C, HID_C, KP2);
    k_prepW<<<(KP3 * 136 + 255) / 256, 256, 0, s2>>>(W3, (__half*)p3h, HID_C, OUT_C, KP3);
    cudaEventRecord(evCSR, s2);

    // join, then the serial layer chain (best-known structure)
    cudaStreamWaitEvent(0, evCSR, 0);
    k_agg128h<true><<<aggGrid, 128>>>((const __half*)pH, (__half*)pHB, b1);
    k_gemm_h<false><<<gemmGrid, 256, GEMM_SMEM>>>((const __half*)pHB, (const __half*)p2h,
                                                  (__half*)pH, N_NODES);
    k_agg128h<true><<<aggGrid, 128>>>((const __half*)pH, (__half*)pHB, b2);
    k_gemm_h<true><<<gemmGrid, 256, GEMM_SMEM>>>((const __half*)pHB, (const __half*)p3h,
                                                 (__half*)p48, N_NODES);
    k_agg47h<<<aggGrid, 128>>>(b3, out);
}

// round 17
// speedup vs baseline: 1.1106x; 1.0041x over previous
#include <cuda_runtime.h>
#include <cuda_bf16.h>
#include <cuda_fp16.h>
#include <cstdint>

#define N_NODES 50000
#define N_EDGES 1600000
#define IN_C    1433
#define HID_C   128
#define OUT_C   47

#define KP1 1472   // 23 chunks * 64
#define KP2 128
#define KP3 128

// ---------------- scratch (static device globals; no runtime alloc) ----------
__device__ int   g_cnt[N_NODES];
__device__ int   g_rowptr[N_NODES + 1];
__device__ int   g_cursor[N_NODES];
__device__ int   g_srce[N_EDGES];
__device__ float g_dinv[N_NODES];
__device__ int   g_blksum[256];
__device__ int   g_blkoff[256];
__device__ __align__(16) __half g_bufH [(size_t)N_NODES * HID_C]; // gemm1/2 out (gather src), stride 128
__device__ __align__(16) __half g_bufHB[(size_t)N_NODES * HID_C]; // agg out h (gemm2/3 A), stride 128
__device__ __align__(16) __half g_buf48[(size_t)N_NODES * 48];    // gemm3 out, stride 48
// pre-converted weights, padded [KP][136] fp16
__device__ __align__(16) __half g_W1h[KP1 * 136];
__device__ __align__(16) __half g_W2h[KP2 * 136];
__device__ __align__(16) __half g_W3h[KP3 * 136];

// ---------------- graph preprocessing -----------------------------------
__global__ void k_hist(const int* __restrict__ ei) {
    int e = blockIdx.x * blockDim.x + threadIdx.x;
    if (e < N_EDGES) atomicAdd(&g_cnt[ei[N_EDGES + e]], 1);
}
__global__ void k_scan1() {
    __shared__ int sw[8];
    int i = blockIdx.x * 256 + threadIdx.x;
    int v = (i < N_NODES) ? g_cnt[i] : 0;
    int lane = threadIdx.x & 31, wid = threadIdx.x >> 5;
    #pragma unroll
    for (int o = 16; o > 0; o >>= 1) v += __shfl_down_sync(0xffffffffu, v, o);
    if (lane == 0) sw[wid] = v;
    __syncthreads();
    if (wid == 0) {
        int s = (lane < 8) ? sw[lane] : 0;
        #pragma unroll
        for (int o = 4; o > 0; o >>= 1) s += __shfl_down_sync(0xffu, s, o);
        if (lane == 0) g_blksum[blockIdx.x] = s;
    }
}
__global__ void k_scan2(int nblk) {
    __shared__ int sw[8];
    int t = threadIdx.x, lane = t & 31, wid = t >> 5;
    int v = (t < nblk) ? g_blksum[t] : 0;
    int x = v;
    #pragma unroll
    for (int o = 1; o < 32; o <<= 1) { int y = __shfl_up_sync(0xffffffffu, x, o); if (lane >= o) x += y; }
    if (lane == 31) sw[wid] = x;
    __syncthreads();
    if (wid == 0 && lane < 8) {
        int wx = sw[lane];
        #pragma unroll
        for (int o = 1; o < 8; o <<= 1) { int y = __shfl_up_sync(0xffu, wx, o); if (lane >= o) wx += y; }
        sw[lane] = wx;
    }
    __syncthreads();
    int excl = x - v + (wid ? sw[wid - 1] : 0);
    if (t < nblk) g_blkoff[t] = excl;
}
__global__ void k_scan3() {   // also computes dinv
    __shared__ int sw[8];
    int i = blockIdx.x * 256 + threadIdx.x;
    int t = threadIdx.x, lane = t & 31, wid = t >> 5;
    int v = (i < N_NODES) ? g_cnt[i] : 0;
    int x = v;
    #pragma unroll
    for (int o = 1; o < 32; o <<= 1) { int y = __shfl_up_sync(0xffffffffu, x, o); if (lane >= o) x += y; }
    if (lane == 31) sw[wid] = x;
    __syncthreads();
    if (wid == 0 && lane < 8) {
        int wx = sw[lane];
        #pragma unroll
        for (int o = 1; o < 8; o <<= 1) { int y = __shfl_up_sync(0xffu, wx, o); if (lane >= o) wx += y; }
        sw[lane] = wx;
    }
    __syncthreads();
    int excl = x - v + (wid ? sw[wid - 1] : 0) + g_blkoff[blockIdx.x];
    if (i < N_NODES) {
        g_rowptr[i] = excl; g_cursor[i] = excl;
        g_dinv[i] = rsqrtf((float)v + 1.0f);
    }
    if (i == 0) g_rowptr[N_NODES] = N_EDGES;
}
__global__ void k_fill(const int* __restrict__ ei) {
    int e = blockIdx.x * blockDim.x + threadIdx.x;
    if (e < N_EDGES) {
        int s = ei[e];
        int d = ei[N_EDGES + e];
        int p = atomicAdd(&g_cursor[d], 1);
        g_srce[p] = s;
    }
}

// ---------------- weight prepass: fp32 W[K,Nact] -> fp16 [KP][136] -----------
__global__ void k_prepW(const float* __restrict__ W,
                        __half* __restrict__ oh, int K, int Nact, int KP) {
    int i = blockIdx.x * 256 + threadIdx.x;
    if (i >= KP * 136) return;
    int k = i / 136, n = i - k * 136;
    float v = (k < K && n < Nact) ? W[(size_t)k * Nact + n] : 0.f;
    oh[i] = __float2half_rn(v);
}

// ---------------- shared GEMM plumbing ---------------------------------------
#define B_ST 136
// K-chunk-64 stage layout (used by all GEMMs):
#define A_ST1 72
#define OFF_BH1 9216           // A: 64*72*2
#define STAGE_B1 26624         // + B: 64*136*2 = 17408 B
#define GEMM1_SMEM (2 * STAGE_B1)

__device__ __forceinline__ uint32_t smem_u32(const void* p) {
    uint32_t a;
    asm("{ .reg .u64 t; cvta.to.shared.u64 t, %1; cvt.u32.u64 %0, t; }" : "=r"(a) : "l"(p));
    return a;
}
__device__ __forceinline__ void cpa16(uint32_t dst, const void* src) {
    asm volatile("cp.async.cg.shared.global [%0], [%1], 16;" :: "r"(dst), "l"(src));
}
__device__ __forceinline__ void cpa16z(uint32_t dst, const void* src, bool ok) {
    int sz = ok ? 16 : 0;
    asm volatile("cp.async.cg.shared.global [%0], [%1], 16, %2;" :: "r"(dst), "l"(src), "r"(sz));
}
#define CP_COMMIT() asm volatile("cp.async.commit_group;" ::: "memory")
#define CP_WAIT0()  asm volatile("cp.async.wait_group 0;" ::: "memory")

__device__ __forceinline__ void ldmx4(uint32_t* r, uint32_t addr) {
    asm volatile("ldmatrix.sync.aligned.m8n8.x4.shared.b16 {%0,%1,%2,%3}, [%4];"
        : "=r"(r[0]), "=r"(r[1]), "=r"(r[2]), "=r"(r[3]) : "r"(addr));
}
__device__ __forceinline__ void ldmx4t(uint32_t* r, uint32_t addr) {
    asm volatile("ldmatrix.sync.aligned.m8n8.x4.trans.shared.b16 {%0,%1,%2,%3}, [%4];"
        : "=r"(r[0]), "=r"(r[1]), "=r"(r[2]), "=r"(r[3]) : "r"(addr));
}
__device__ __forceinline__ void mma16816h(float* d, const uint32_t* a, const uint32_t* b) {
    asm volatile(
        "mma.sync.aligned.m16n8k16.row.col.f32.f16.f16.f32 "
        "{%0,%1,%2,%3}, {%4,%5,%6,%7}, {%8,%9}, {%0,%1,%2,%3};"
        : "+f"(d[0]), "+f"(d[1]), "+f"(d[2]), "+f"(d[3])
        : "r"(a[0]), "r"(a[1]), "r"(a[2]), "r"(a[3]), "r"(b[0]), "r"(b[1]));
}

// ---------------- GEMM1: fp32 A (LDG+convert), fp16 C, K-chunk 64 ------------
__global__ __launch_bounds__(256, 3) void k_gemm1(
    const float* __restrict__ A, const __half* __restrict__ Wh,
    __half* __restrict__ C, int M, int K)
{
    extern __shared__ char smp[];
    const uint32_t sbase = smem_u32(smp);

    const int tid = threadIdx.x, lane = tid & 31, warp = tid >> 5;
    const int wm = warp >> 2, wn = warp & 3;
    const int rowBase = blockIdx.x * 64;

    const int grp = lane >> 3;
    const uint32_t aLane  = (uint32_t)((((grp & 1) * 8 + (lane & 7)) * A_ST1 + (grp >> 1) * 8) * 2);
    const uint32_t bLaneT = (uint32_t)(((lane & 15) * B_ST) * 2) + (uint32_t)(wn * 64)
                          + (uint32_t)(((lane >> 4) & 1) * 16);

    float acc[2][4][4];
    #pragma unroll
    for (int i = 0; i < 2; i++)
        #pragma unroll
        for (int j = 0; j < 4; j++)
            #pragma unroll
            for (int r = 0; r < 4; r++) acc[i][j][r] = 0.f;

    const int NC = (K + 63) / 64;    // 23
    float aReg[16];

    const int aRow = tid >> 4;          // 0..15
    const int aK   = (tid & 15) * 2;    // 0..30, pairs within a 32-k half

    auto copyB = [&](int c, uint32_t st) {
        const char* sH = (const char*)(Wh + (size_t)c * 64 * 136);
        uint32_t dH = st + OFF_BH1;
        #pragma unroll
        for (int u = 0; u < 5; u++) {
            int i = u * 256 + tid;
            if (i < 1088) cpa16(dH + (uint32_t)i * 16, sH + i * 16);
        }
    };
    auto loadA = [&](int c) {
        const int k0 = c * 64;
        #pragma unroll
        for (int u = 0; u < 4; u++) {
            int m = u * 16 + aRow;
            int gm = rowBase + m;
            bool okm = (gm < M);
            const float* ap = A + (size_t)(okm ? gm : 0) * K;
            #pragma unroll
            for (int h = 0; h < 2; h++) {
                int gk = k0 + h * 32 + aK;
                aReg[(u * 2 + h) * 2]     = (okm && gk     < K) ? __ldg(&ap[gk])     : 0.f;
                aReg[(u * 2 + h) * 2 + 1] = (okm && gk + 1 < K) ? __ldg(&ap[gk + 1]) : 0.f;
            }
        }
    };
    auto convA = [&](uint32_t st) {
        __half* ah = (__half*)(smp + (st - sbase));
        #pragma unroll
        for (int u = 0; u < 4; u++) {
            int m = u * 16 + aRow;
            #pragma unroll
            for (int h = 0; h < 2; h++) {
                __half2 hh = __floats2half2_rn(aReg[(u * 2 + h) * 2], aReg[(u * 2 + h) * 2 + 1]);
                *(__half2*)&ah[m * A_ST1 + h * 32 + aK] = hh;
            }
        }
    };

    copyB(0, sbase);
    CP_COMMIT();
    loadA(0);
    convA(sbase);
    CP_WAIT0();

    for (int c = 0; c < NC; c++) {
        __syncthreads();
        const uint32_t stN = sbase + (uint32_t)((c + 1) & 1) * STAGE_B1;
        const bool more = (c + 1 < NC);
        if (more) copyB(c + 1, stN);
        CP_COMMIT();
        if (more) loadA(c + 1);

        const uint32_t st = sbase + (uint32_t)(c & 1) * STAGE_B1;
        const uint32_t uAh = st, uBh = st + OFF_BH1;
        #pragma unroll
        for (int ks = 0; ks < 4; ks++) {
            uint32_t bh[4][2];
            #pragma unroll
            for (int p = 0; p < 2; p++) {
                uint32_t r4[4];
                ldmx4t(r4, uBh + (uint32_t)(ks * 16 * B_ST * 2) + bLaneT + (uint32_t)(p * 32));
                bh[2 * p][0] = r4[0]; bh[2 * p][1] = r4[1];
                bh[2 * p + 1][0] = r4[2]; bh[2 * p + 1][1] = r4[3];
            }
            #pragma unroll
            for (int mt = 0; mt < 2; mt++) {
                uint32_t ao = aLane + (uint32_t)(((wm * 32 + mt * 16) * A_ST1 + ks * 16) * 2);
                uint32_t ah[4];
                ldmx4(ah, uAh + ao);
                #pragma unroll
                for (int nt = 0; nt < 4; nt++) mma16816h(acc[mt][nt], ah, bh[nt]);
            }
        }

        if (more) convA(stN);
        CP_WAIT0();
    }

    const int r = lane >> 2, cc = (lane & 3) * 2;
    #pragma unroll
    for (int mt = 0; mt < 2; mt++) {
        int m0 = rowBase + wm * 32 + mt * 16 + r;
        #pragma unroll
        for (int nt = 0; nt < 4; nt++) {
            int n0 = wn * 32 + nt * 8 + cc;
            if (m0 < M)
                *(__half2*)(C + (size_t)m0 * 128 + n0) = __floats2half2_rn(acc[mt][nt][0], acc[mt][nt][1]);
            if (m0 + 8 < M)
                *(__half2*)(C + (size_t)(m0 + 8) * 128 + n0) = __floats2half2_rn(acc[mt][nt][2], acc[mt][nt][3]);
        }
    }
}

// ---------------- GEMM2/3: fp16 A (pure cp.async), fp16 C, K-chunk 64 --------
template<bool C48>
__global__ __launch_bounds__(256, 3) void k_gemm_h(
    const __half* __restrict__ A,   // [M,128] fp16
    const __half* __restrict__ Wh,
    __half* __restrict__ C, int M)
{
    extern __shared__ char smp[];
    const uint32_t sbase = smem_u32(smp);

    const int tid = threadIdx.x, lane = tid & 31, warp = tid >> 5;
    const int wm = warp >> 2, wn = warp & 3;
    const int rowBase = blockIdx.x * 64;

    const int grp = lane >> 3;
    const uint32_t aLane  = (uint32_t)((((grp & 1) * 8 + (lane & 7)) * A_ST1 + (grp >> 1) * 8) * 2);
    const uint32_t bLaneT = (uint32_t)(((lane & 15) * B_ST) * 2) + (uint32_t)(wn * 64)
                          + (uint32_t)(((lane >> 4) & 1) * 16);

    float acc[2][4][4];
    #pragma unroll
    for (int i = 0; i < 2; i++)
        #pragma unroll
        for (int j = 0; j < 4; j++)
            #pragma unroll
            for (int r = 0; r < 4; r++) acc[i][j][r] = 0.f;

    const int NC = 2;  // K = 128, chunk 64

    auto copyAB = [&](int c, uint32_t st) {
        // A: 64 rows x 64 halfs = 8 x 16B per row -> 512 cps, 2 per thread
        #pragma unroll
        for (int u = 0; u < 2; u++) {
            int idx = u * 256 + tid;
            int m = idx >> 3, j = idx & 7;
            int gm = rowBase + m;
            const char* srcA = (const char*)(A + (size_t)(gm < M ? gm : 0) * 128 + c * 64 + j * 8);
            cpa16z(st + (uint32_t)(m * (A_ST1 * 2) + j * 16), srcA, gm < M);
        }
        // B: 64 k-rows x 136 halfs = 1088 x 16B
        const char* sH = (const char*)(Wh + (size_t)c * 64 * 136);
        uint32_t dH = st + OFF_BH1;
        #pragma unroll
        for (int u = 0; u < 5; u++) {
            int i = u * 256 + tid;
            if (i < 1088) cpa16(dH + (uint32_t)i * 16, sH + i * 16);
        }
    };

    copyAB(0, sbase);
    CP_COMMIT();
    CP_WAIT0();

    #pragma unroll
    for (int c = 0; c < NC; c++) {
        __syncthreads();
        const uint32_t stN = sbase + (uint32_t)((c + 1) & 1) * STAGE_B1;
        const bool more = (c + 1 < NC);
        if (more) copyAB(c + 1, stN);
        CP_COMMIT();

        const uint32_t st = sbase + (uint32_t)(c & 1) * STAGE_B1;
        const uint32_t uAh = st, uBh = st + OFF_BH1;
        #pragma unroll
        for (int ks = 0; ks < 4; ks++) {
            uint32_t bh[4][2];
            #pragma unroll
            for (int p = 0; p < 2; p++) {
                uint32_t r4[4];
                ldmx4t(r4, uBh + (uint32_t)(ks * 16 * B_ST * 2) + bLaneT + (uint32_t)(p * 32));
                bh[2 * p][0] = r4[0]; bh[2 * p][1] = r4[1];
                bh[2 * p + 1][0] = r4[2]; bh[2 * p + 1][1] = r4[3];
            }
            #pragma unroll
            for (int mt = 0; mt < 2; mt++) {
                uint32_t ao = aLane + (uint32_t)(((wm * 32 + mt * 16) * A_ST1 + ks * 16) * 2);
                uint32_t ah[4];
                ldmx4(ah, uAh + ao);
                #pragma unroll
                for (int nt = 0; nt < 4; nt++) mma16816h(acc[mt][nt], ah, bh[nt]);
            }
        }
        CP_WAIT0();
    }

    const int r = lane >> 2, cc = (lane & 3) * 2;
    #pragma unroll
    for (int mt = 0; mt < 2; mt++) {
        int m0 = rowBase + wm * 32 + mt * 16 + r;
        #pragma unroll
        for (int nt = 0; nt < 4; nt++) {
            int n0 = wn * 32 + nt * 8 + cc;
            if (C48) {
                if (n0 < 48) {
                    if (m0 < M)
                        *(__half2*)(C + (size_t)m0 * 48 + n0) = __floats2half2_rn(acc[mt][nt][0], acc[mt][nt][1]);
                    if (m0 + 8 < M)
                        *(__half2*)(C + (size_t)(m0 + 8) * 48 + n0) = __floats2half2_rn(acc[mt][nt][2], acc[mt][nt][3]);
                }
            } else {
                if (m0 < M)
                    *(__half2*)(C + (size_t)m0 * 128 + n0) = __floats2half2_rn(acc[mt][nt][0], acc[mt][nt][1]);
                if (m0 + 8 < M)
                    *(__half2*)(C + (size_t)(m0 + 8) * 128 + n0) = __floats2half2_rn(acc[mt][nt][2], acc[mt][nt][3]);
            }
        }
    }
}

// ---------------- aggregation (fp16 gather, fp32 accum, fp16 h out) ----------
template<bool RELU>
__global__ __launch_bounds__(128) void k_agg128h(
    const __half* __restrict__ hw, __half* __restrict__ out,
    const float* __restrict__ bias)
{
    __shared__ int   s_idx[4][32];
    __shared__ float s_wt [4][32];

    int w    = threadIdx.x >> 5;
    int lane = threadIdx.x & 31;
    int node = blockIdx.x * 4 + w;
    if (node >= N_NODES) return;

    int beg = g_rowptr[node];
    int end = g_rowptr[node + 1];
    float dd = g_dinv[node];

    float ax = 0.f, ay = 0.f, az = 0.f, aw = 0.f;

    for (int base = beg; base < end; base += 32) {
        int n = end - base; if (n > 32) n = 32;
        int si = 0; float swt = 0.f;
        if (lane < n) { si = g_srce[base + lane]; swt = g_dinv[si] * dd; }
        s_idx[w][lane] = si; s_wt[w][lane] = swt;
        __syncwarp();
        if (n == 32) {
            #pragma unroll 8
            for (int j = 0; j < 32; j++) {
                int ss = s_idx[w][j]; float ww = s_wt[w][j];
                uint2 raw = *(const uint2*)(hw + (size_t)ss * 128 + lane * 4);
                float2 f0 = __half22float2(*(__half2*)&raw.x);
                float2 f1 = __half22float2(*(__half2*)&raw.y);
                ax += f0.x * ww; ay += f0.y * ww; az += f1.x * ww; aw += f1.y * ww;
            }
        } else {
            for (int j = 0; j < n; j++) {
                int ss = s_idx[w][j]; float ww = s_wt[w][j];
                uint2 raw = *(const uint2*)(hw + (size_t)ss * 128 + lane * 4);
                float2 f0 = __half22float2(*(__half2*)&raw.x);
                float2 f1 = __half22float2(*(__half2*)&raw.y);
                ax += f0.x * ww; ay += f0.y * ww; az += f1.x * ww; aw += f1.y * ww;
            }
        }
        __syncwarp();
    }

    {   // self-loop
        float ww = dd * dd;
        uint2 raw = *(const uint2*)(hw + (size_t)node * 128 + lane * 4);
        float2 f0 = __half22float2(*(__half2*)&raw.x);
        float2 f1 = __half22float2(*(__half2*)&raw.y);
        ax += f0.x * ww; ay += f0.y * ww; az += f1.x * ww; aw += f1.y * ww;
    }
    float4 b = *(const float4*)(bias + lane * 4);
    ax += b.x; ay += b.y; az += b.z; aw += b.w;
    if (RELU) {
        ax = fmaxf(ax, 0.f); ay = fmaxf(ay, 0.f);
        az = fmaxf(az, 0.f); aw = fmaxf(aw, 0.f);
    }
    __half2 o0 = __floats2half2_rn(ax, ay);
    __half2 o1 = __floats2half2_rn(az, aw);
    uint2 pk = { *(uint32_t*)&o0, *(uint32_t*)&o1 };
    *(uint2*)(out + (size_t)node * 128 + lane * 4) = pk;
}

// final layer: gather fp16 stride-48 rows, fp32 out
__global__ __launch_bounds__(128) void k_agg47h(const float* __restrict__ bias,
                                                float* __restrict__ out) {
    const __half* hw = g_buf48;   // stride 48 halfs
    __shared__ int   s_idx[4][32];
    __shared__ float s_wt [4][32];

    int w    = threadIdx.x >> 5;
    int lane = threadIdx.x & 31;
    int node = blockIdx.x * 4 + w;
    if (node >= N_NODES) return;

    int beg = g_rowptr[node];
    int end = g_rowptr[node + 1];
    float dd = g_dinv[node];
    bool act = (lane < 24);       // lanes 0-23 cover 48 cols as half2

    float a0 = 0.f, a1 = 0.f;

    for (int base = beg; base < end; base += 32) {
        int n = end - base; if (n > 32) n = 32;
        int si = 0; float swt = 0.f;
        if (lane < n) { si = g_srce[base + lane]; swt = g_dinv[si] * dd; }
        s_idx[w][lane] = si; s_wt[w][lane] = swt;
        __syncwarp();
        for (int j = 0; j < n; j++) {
            int ss = s_idx[w][j]; float ww = s_wt[w][j];
            if (act) {
                uint32_t raw = *(const uint32_t*)(hw + (size_t)ss * 48 + lane * 2);
                float2 f = __half22float2(*(__half2*)&raw);
                a0 += f.x * ww; a1 += f.y * ww;
            }
        }
        __syncwarp();
    }
    {   // self-loop
        float ww = dd * dd;
        if (act) {
            uint32_t raw = *(const uint32_t*)(hw + (size_t)node * 48 + lane * 2);
            float2 f = __half22float2(*(__half2*)&raw);
            a0 += f.x * ww; a1 += f.y * ww;
        }
    }
    if (act) {
        int c0 = lane * 2;
        out[(size_t)node * OUT_C + c0] = a0 + bias[c0];
        if (c0 + 1 < OUT_C)
            out[(size_t)node * OUT_C + c0 + 1] = a1 + bias[c0 + 1];
    }
}

// ---------------- launch ------------------------------------------------
extern "C" void kernel_launch(void* const* d_in, const int* in_sizes, int n_in,
                              void* d_out, int out_size) {
    const float* x  = (const float*)d_in[0];
    const int*   ei = (const int*)  d_in[1];
    const float* W1 = (const float*)d_in[2];
    const float* b1 = (const float*)d_in[3];
    const float* W2 = (const float*)d_in[4];
    const float* b2 = (const float*)d_in[5];
    const float* W3 = (const float*)d_in[6];
    const float* b3 = (const float*)d_in[7];
    float* out = (float*)d_out;

    void *pH, *pHB, *p48, *p1h, *p2h, *p3h, *pCnt;
    cudaGetSymbolAddress(&pH,  g_bufH);
    cudaGetSymbolAddress(&pHB, g_bufHB);
    cudaGetSymbolAddress(&p48, g_buf48);
    cudaGetSymbolAddress(&p1h, g_W1h);
    cudaGetSymbolAddress(&p2h, g_W2h);
    cudaGetSymbolAddress(&p3h, g_W3h);
    cudaGetSymbolAddress(&pCnt, g_cnt);

    cudaFuncSetAttribute((const void*)&k_gemm1,         cudaFuncAttributeMaxDynamicSharedMemorySize, GEMM1_SMEM);
    cudaFuncSetAttribute((const void*)&k_gemm_h<false>, cudaFuncAttributeMaxDynamicSharedMemorySize, GEMM1_SMEM);
    cudaFuncSetAttribute((const void*)&k_gemm_h<true>,  cudaFuncAttributeMaxDynamicSharedMemorySize, GEMM1_SMEM);

    static cudaStream_t s2 = nullptr;
    static cudaEvent_t evFork = nullptr, evCSR = nullptr;
    if (!s2) {
        cudaStreamCreateWithFlags(&s2, cudaStreamNonBlocking);
        cudaEventCreateWithFlags(&evFork, cudaEventDisableTiming);
        cudaEventCreateWithFlags(&evCSR,  cudaEventDisableTiming);
    }

    const int NB = (N_NODES + 255) / 256;
    const int EB = (N_EDGES + 255) / 256;
    const int gemmGrid = (N_NODES + 63) / 64;    // 782
    const int aggGrid  = (N_NODES + 3) / 4;

    // fork side stream at t=0: full CSR build + weight prep 2/3
    cudaEventRecord(evFork, 0);
    cudaStreamWaitEvent(s2, evFork, 0);
    cudaMemsetAsync(pCnt, 0, N_NODES * sizeof(int), s2);
    k_hist<<<EB, 256, 0, s2>>>(ei);
    // main: GEMM1 path immediately
    k_prepW<<<(KP1 * 136 + 255) / 256, 256>>>(W1, (__half*)p1h, IN_C, HID_C, KP1);
    k_gemm1<<<gemmGrid, 256, GEMM1_SMEM>>>(x, (const __half*)p1h,
                                           (__half*)pH, N_NODES, IN_C);
    // side stream: rest of CSR + weight prep
    k_scan1<<<NB, 256, 0, s2>>>();
    k_scan2<<<1, 256, 0, s2>>>(NB);
    k_scan3<<<NB, 256, 0, s2>>>();
    k_fill<<<EB, 256, 0, s2>>>(ei);
    k_prepW<<<(KP2 * 136 + 255) / 256, 256, 0, s2>>>(W2, (__half*)p2h, HID_C, HID_C, KP2);
    k_prepW<<<(KP3 * 136 + 255) / 256, 256, 0, s2>>>(W3, (__half*)p3h, HID_C, OUT_C, KP3);
    cudaEventRecord(evCSR, s2);

    // join, then the serial layer chain
    cudaStreamWaitEvent(0, evCSR, 0);
    k_agg128h<true><<<aggGrid, 128>>>((const __half*)pH, (__half*)pHB, b1);
    k_gemm_h<false><<<gemmGrid, 256, GEMM1_SMEM>>>((const __half*)pHB, (const __half*)p2h,
                                                   (__half*)pH, N_NODES);
    k_agg128h<true><<<aggGrid, 128>>>((const __half*)pH, (__half*)pHB, b2);
    k_gemm_h<true><<<gemmGrid, 256, GEMM1_SMEM>>>((const __half*)pHB, (const __half*)p3h,
                                                  (__half*)p48, N_NODES);
    k_agg47h<<<aggGrid, 128>>>(b3, out);
}